// round 8
// baseline (speedup 1.0000x reference)
#include <cuda_runtime.h>

#define C 32
#define H 128
#define W 256
#define YS 36        // y_sh row stride (144B); bank stride 4 per lane -> conflict-free LDS.128
#define YROWS 257    // rows 0..255 = y columns; row 256 = shared zero row (both boundaries)
#define GO 66
#define GS 67        // bank stride 3 -> conflict-free STS / gather
#define GROWS 259    // rows 256..258 pad the boundary stores (never read)
#define NT 256

typedef unsigned long long u64;

__device__ __forceinline__ u64 pack2(float lo, float hi) {
    u64 r; asm("mov.b64 %0, {%1, %2};" : "=l"(r) : "f"(lo), "f"(hi)); return r;
}
__device__ __forceinline__ void ffma2(u64& acc, u64 a, u64 b) {
    asm("fma.rn.f32x2 %0, %1, %2, %0;" : "+l"(acc) : "l"(a), "l"(b));
}
__device__ __forceinline__ u64 add2(u64 a, u64 b) {
    u64 r; asm("add.rn.f32x2 %0, %1, %2;" : "=l"(r) : "l"(a), "l"(b)); return r;
}
__device__ __forceinline__ float hadd2(u64 v) {
    float lo, hi; asm("mov.b64 {%0, %1}, %2;" : "=f"(lo), "=f"(hi) : "l"(v)); return lo + hi;
}

__global__ __launch_bounds__(NT, 2)
void cost_volume_kernel(const float* __restrict__ x, const float* __restrict__ y,
                        const float* __restrict__ disp, float* __restrict__ out,
                        int D) {
    extern __shared__ float sm[];
    float* y_sh = sm;                  // YROWS * YS  ([col][c]; row 256 = zeros)
    float* G_sh = sm + YROWS * YS;     // GROWS * GS banded Gram

    const int bh = blockIdx.x;
    const int b = bh / H;
    const int h = bh - b * H;
    const int tid = threadIdx.x;
    const size_t HW = (size_t)H * W;
    const float* ybase = y + ((size_t)b * C * H + h) * W;
    const float* xbase = x + ((size_t)b * C * H + h) * W;

    // ---- Phase 1: stage y row transposed (row r = y column r). Row 256 is the
    // zero row implementing the reference's zero-padding mask at BOTH edges.
    {
        const float* src = ybase + tid;
        float* dst = y_sh + tid * YS;
        #pragma unroll
        for (int c = 0; c < C; c += 4) {
            float v0 = src[(size_t)(c + 0) * HW];
            float v1 = src[(size_t)(c + 1) * HW];
            float v2 = src[(size_t)(c + 2) * HW];
            float v3 = src[(size_t)(c + 3) * HW];
            *(float4*)(dst + c) = make_float4(v0, v1, v2, v3);
        }
    }
    if (tid < YS) y_sh[256 * YS + tid] = 0.0f;
    __syncthreads();

    // ---- Phase 2: banded Gram via 4-wide anti-diagonal reuse.
    // Thread (base col w, channel half) loads ONE y row jj = w + o0 - 64 and
    // updates entries (w+i, o0-i), i=0..3; channel halves combined via shfl(16).
    const int lane = tid & 31;
    const int half = lane >> 4;          // c in [16*half, 16*half+16)
    const int wl = lane & 15;
    const int cb = half * 16;

    #pragma unroll 1
    for (int g = 0; g < 2; g++) {
        const int w = ((tid >> 5) << 4) + wl + g * 128;   // base col 0..255
        // x for cols w..w+3, this half's 16 channels, packed as pairs.
        u64 xr[4][8];
        #pragma unroll
        for (int i = 0; i < 4; i++) {
            int col = w + i;
            bool valid = (col < W);
            const float* xc = xbase + (valid ? col : 0);
            #pragma unroll
            for (int k = 0; k < 8; k++) {
                float a0 = valid ? xc[(size_t)(cb + 2 * k) * HW] : 0.f;
                float a1 = valid ? xc[(size_t)(cb + 2 * k + 1) * HW] : 0.f;
                xr[i][k] = pack2(a0, a1);
            }
        }
        #pragma unroll 1
        for (int o0 = 3; o0 <= 67; o0 += 4) {
            int r = w + o0 - 64;
            if ((unsigned)r > 255u) r = 256;         // both boundaries -> zero row
            const ulonglong2* yp = (const ulonglong2*)(y_sh + r * YS + cb);
            ulonglong2 q0 = yp[0], q1 = yp[1], q2 = yp[2], q3 = yp[3];
            float s[4];
            #pragma unroll
            for (int i = 0; i < 4; i++) {
                u64 a = 0, bq = 0;
                ffma2(a,  xr[i][0], q0.x);  ffma2(bq, xr[i][1], q0.y);
                ffma2(a,  xr[i][2], q1.x);  ffma2(bq, xr[i][3], q1.y);
                ffma2(a,  xr[i][4], q2.x);  ffma2(bq, xr[i][5], q2.y);
                ffma2(a,  xr[i][6], q3.x);  ffma2(bq, xr[i][7], q3.y);
                s[i] = hadd2(add2(a, bq));
                s[i] += __shfl_xor_sync(0xFFFFFFFFu, s[i], 16);
            }
            if (half == 0) {
                if (o0 != 67) {                       // o=67/66 out of band
                    G_sh[w * GS + o0] = s[0];
                    G_sh[(w + 1) * GS + (o0 - 1)] = s[1];
                }
            } else {
                G_sh[(w + 2) * GS + (o0 - 2)] = s[2]; // rows <= 258 (padded)
                G_sh[(w + 3) * GS + (o0 - 3)] = s[3];
            }
        }
    }
    // Cleanup: entries (v, o) with v < (3-o)&3, v in {0,1,2} (99 entries),
    // disjoint from main-loop writes.
    if (tid < 3 * 66) {
        int v = tid / 66;
        int o = tid - v * 66;
        int ineed = (3 - o) & 3;
        if (ineed > v) {
            int r = v + o - 64;
            if ((unsigned)r > 255u) r = 256;
            float s = 0.f;
            #pragma unroll
            for (int c = 0; c < C; c++)
                s = fmaf(xbase[(size_t)c * HW + v], y_sh[r * YS + c], s);
            G_sh[v * GS + o] = s;
        }
    }

    // ---- Phase 3 prologue: disp loads before the barrier (latency hidden
    // under other warps' phase-2 tail).
    const float* dbase = disp + ((size_t)b * D * H + h) * W;
    float* obase = out + ((size_t)b * D * H + h) * W;

    if (D == 48) {
        float4 dv[12];
        #pragma unroll
        for (int k = 0; k < 12; k++) {
            int i = tid + k * NT;
            int d = i >> 6;               // 64 float4 per d
            int w4 = (i & 63) << 2;
            dv[k] = *(const float4*)(dbase + (size_t)d * HW + w4);
        }
        __syncthreads();
        #pragma unroll
        for (int k = 0; k < 12; k++) {
            int i = tid + k * NT;
            int d = i >> 6;
            int w4 = (i & 63) << 2;
            float4 res;
            #pragma unroll
            for (int j = 0; j < 4; j++) {
                int ww = w4 + j;
                float px = (float)ww - (&dv[k].x)[j];
                float x0f = floorf(px);
                float fx = px - x0f;
                int o = (int)x0f - ww + 64;
                float g0 = ((unsigned)o < GO) ? G_sh[ww * GS + o] : 0.f;
                float g1 = ((unsigned)(o + 1) < GO) ? G_sh[ww * GS + o + 1] : 0.f;
                (&res.x)[j] = (g0 + (g1 - g0) * fx) * (1.0f / C);
            }
            *(float4*)(obase + (size_t)d * HW + w4) = res;
        }
    } else {
        __syncthreads();
        const int total4 = D * (W / 4);
        #pragma unroll 4
        for (int i = tid; i < total4; i += NT) {
            int d = i >> 6;
            int w4 = (i & 63) << 2;
            float4 dvv = *(const float4*)(dbase + (size_t)d * HW + w4);
            float4 res;
            #pragma unroll
            for (int j = 0; j < 4; j++) {
                int ww = w4 + j;
                float px = (float)ww - (&dvv.x)[j];
                float x0f = floorf(px);
                float fx = px - x0f;
                int o = (int)x0f - ww + 64;
                float g0 = ((unsigned)o < GO) ? G_sh[ww * GS + o] : 0.f;
                float g1 = ((unsigned)(o + 1) < GO) ? G_sh[ww * GS + o + 1] : 0.f;
                (&res.x)[j] = (g0 + (g1 - g0) * fx) * (1.0f / C);
            }
            *(float4*)(obase + (size_t)d * HW + w4) = res;
        }
    }
}

extern "C" void kernel_launch(void* const* d_in, const int* in_sizes, int n_in,
                              void* d_out, int out_size) {
    const float* x = (const float*)d_in[0];
    const float* y = (const float*)d_in[1];
    const float* disp = (const float*)d_in[2];
    int B = in_sizes[0] / (C * H * W);
    int D = in_sizes[2] / (B * H * W);
    int smem = (YROWS * YS + GROWS * GS) * (int)sizeof(float);
    cudaFuncSetAttribute(cost_volume_kernel,
                         cudaFuncAttributeMaxDynamicSharedMemorySize, smem);
    cost_volume_kernel<<<B * H, NT, smem>>>(x, y, disp, (float*)d_out, D);
}